// round 3
// baseline (speedup 1.0000x reference)
#include <cuda_runtime.h>

// IFOPooling: h_t = f_t * h_{t-1} + i_t * z_t over seq (last dim, contiguous).
// [B=16, H=1024, S=2048] fp32 -> 16384 rows of 2048.
//
// R3: warp-per-row, chunked affine scan. No smem, no __syncthreads.
// Each warp processes one row in 8 chunks of 256 elements (lane*8 each).
// Cross-chunk state is a single scalar carry; all loads/scans within a chunk
// are carry-independent, so unrolling lets ptxas keep LDGs in flight across
// the shuffle chains and stores.

#define SEQ   2048
#define TPB   256
#define EPT   8                    // elements per lane per chunk
#define CHUNK (32 * EPT)           // 256 elements per chunk
#define NCHUNK (SEQ / CHUNK)       // 8
#define WPB   (TPB / 32)           // 8 warps per CTA -> 2048 CTAs

__global__ __launch_bounds__(TPB, 5) void ifo_scan_kernel(
    const float* __restrict__ f,
    const float* __restrict__ z,
    const float* __restrict__ ig,
    float* __restrict__ out)
{
    const int warp_global = blockIdx.x * WPB + (threadIdx.x >> 5);
    const unsigned lane = threadIdx.x & 31u;
    const int base = warp_global * SEQ + (int)lane * EPT;

    float carry = 0.0f;   // h entering the current chunk

    #pragma unroll
    for (int c = 0; c < NCHUNK; c++) {
        const int off = base + c * CHUNK;

        // ---- coalesced streaming vector loads (carry-independent) ----
        float4 fa = __ldcs(reinterpret_cast<const float4*>(f  + off));
        float4 fb = __ldcs(reinterpret_cast<const float4*>(f  + off + 4));
        float4 za = __ldcs(reinterpret_cast<const float4*>(z  + off));
        float4 zb = __ldcs(reinterpret_cast<const float4*>(z  + off + 4));
        float4 ia = __ldcs(reinterpret_cast<const float4*>(ig + off));
        float4 ib = __ldcs(reinterpret_cast<const float4*>(ig + off + 4));

        float fv[EPT] = {fa.x, fa.y, fa.z, fa.w, fb.x, fb.y, fb.z, fb.w};
        float xv[EPT];
        xv[0] = ia.x * za.x; xv[1] = ia.y * za.y; xv[2] = ia.z * za.z; xv[3] = ia.w * za.w;
        xv[4] = ib.x * zb.x; xv[5] = ib.y * zb.y; xv[6] = ib.z * zb.z; xv[7] = ib.w * zb.w;

        // ---- local segment composite (F, X): h_out = F*h_in + X ----
        float F = 1.0f, X = 0.0f;
        #pragma unroll
        for (int j = 0; j < EPT; j++) {
            X = fmaf(fv[j], X, xv[j]);
            F *= fv[j];
        }

        // ---- inclusive warp scan of composites (carry-independent) ----
        float Fs = F, Xs = X;
        #pragma unroll
        for (int d = 1; d < 32; d <<= 1) {
            float Fo = __shfl_up_sync(0xFFFFFFFFu, Fs, d);
            float Xo = __shfl_up_sync(0xFFFFFFFFu, Xs, d);
            if (lane >= (unsigned)d) {
                Xs = fmaf(Fs, Xo, Xs);     // (Fo,Xo) then (Fs,Xs)
                Fs = Fs * Fo;
            }
        }

        // exclusive composite for this lane = inclusive of lane-1
        float Fex = __shfl_up_sync(0xFFFFFFFFu, Fs, 1);
        float Xex = __shfl_up_sync(0xFFFFFFFFu, Xs, 1);
        if (lane == 0) { Fex = 1.0f; Xex = 0.0f; }

        // whole-chunk composite from lane 31 (for next chunk's carry)
        float Ftot = __shfl_sync(0xFFFFFFFFu, Fs, 31);
        float Xtot = __shfl_sync(0xFFFFFFFFu, Xs, 31);

        // ---- apply carry, replay, store ----
        float h = fmaf(Fex, carry, Xex);
        float r[EPT];
        #pragma unroll
        for (int j = 0; j < EPT; j++) {
            h = fmaf(fv[j], h, xv[j]);
            r[j] = h;
        }
        float4 oa = {r[0], r[1], r[2], r[3]};
        float4 ob = {r[4], r[5], r[6], r[7]};
        __stcs(reinterpret_cast<float4*>(out + off),     oa);
        __stcs(reinterpret_cast<float4*>(out + off + 4), ob);

        carry = fmaf(Ftot, carry, Xtot);
    }
}

extern "C" void kernel_launch(void* const* d_in, const int* in_sizes, int n_in,
                              void* d_out, int out_size)
{
    const float* f  = (const float*)d_in[0];
    const float* z  = (const float*)d_in[1];
    const float* ig = (const float*)d_in[2];
    float* out = (float*)d_out;

    const int rows = out_size / SEQ;        // 16384
    const int ctas = rows / WPB;            // 2048
    ifo_scan_kernel<<<ctas, TPB>>>(f, z, ig, out);
}

// round 4
// speedup vs baseline: 1.0078x; 1.0078x over previous
#include <cuda_runtime.h>

// IFOPooling: h_t = f_t * h_{t-1} + i_t * z_t over seq (last dim, contiguous).
// [B=16, H=1024, S=2048] fp32 -> 16384 rows of 2048.
//
// R4: block-per-row (proven best shape), TPB=128, EPT=16.
// 12 front-batched LDG.128 per thread for deep MLP; single tiny smem scan
// over 4 warp aggregates; big store burst at the end.

#define SEQ 2048
#define TPB 128
#define EPT 16   // elements per thread

__global__ __launch_bounds__(TPB) void ifo_scan_kernel(
    const float* __restrict__ f,
    const float* __restrict__ z,
    const float* __restrict__ ig,
    float* __restrict__ out)
{
    const int row  = blockIdx.x;
    const int base = row * SEQ;
    const int t    = threadIdx.x;
    const int off  = base + t * EPT;

    // ---- Phase 1: 12 coalesced streaming vector loads, front-batched ----
    float4 f0 = __ldcs(reinterpret_cast<const float4*>(f  + off));
    float4 f1 = __ldcs(reinterpret_cast<const float4*>(f  + off + 4));
    float4 f2 = __ldcs(reinterpret_cast<const float4*>(f  + off + 8));
    float4 f3 = __ldcs(reinterpret_cast<const float4*>(f  + off + 12));
    float4 z0 = __ldcs(reinterpret_cast<const float4*>(z  + off));
    float4 z1 = __ldcs(reinterpret_cast<const float4*>(z  + off + 4));
    float4 z2 = __ldcs(reinterpret_cast<const float4*>(z  + off + 8));
    float4 z3 = __ldcs(reinterpret_cast<const float4*>(z  + off + 12));
    float4 i0 = __ldcs(reinterpret_cast<const float4*>(ig + off));
    float4 i1 = __ldcs(reinterpret_cast<const float4*>(ig + off + 4));
    float4 i2 = __ldcs(reinterpret_cast<const float4*>(ig + off + 8));
    float4 i3 = __ldcs(reinterpret_cast<const float4*>(ig + off + 12));

    float fv[EPT] = {f0.x, f0.y, f0.z, f0.w, f1.x, f1.y, f1.z, f1.w,
                     f2.x, f2.y, f2.z, f2.w, f3.x, f3.y, f3.z, f3.w};
    float xv[EPT];
    xv[0]  = i0.x * z0.x; xv[1]  = i0.y * z0.y; xv[2]  = i0.z * z0.z; xv[3]  = i0.w * z0.w;
    xv[4]  = i1.x * z1.x; xv[5]  = i1.y * z1.y; xv[6]  = i1.z * z1.z; xv[7]  = i1.w * z1.w;
    xv[8]  = i2.x * z2.x; xv[9]  = i2.y * z2.y; xv[10] = i2.z * z2.z; xv[11] = i2.w * z2.w;
    xv[12] = i3.x * z3.x; xv[13] = i3.y * z3.y; xv[14] = i3.z * z3.z; xv[15] = i3.w * z3.w;

    // ---- local segment composite (F, X): h_out = F*h_in + X ----
    float F = 1.0f, X = 0.0f;
    #pragma unroll
    for (int j = 0; j < EPT; j++) {
        X = fmaf(fv[j], X, xv[j]);
        F *= fv[j];
    }

    // ---- Phase 2: inclusive warp scan of composites ----
    const unsigned lane = t & 31u;
    const unsigned warp = t >> 5;
    float Fs = F, Xs = X;
    #pragma unroll
    for (int d = 1; d < 32; d <<= 1) {
        float Fo = __shfl_up_sync(0xFFFFFFFFu, Fs, d);
        float Xo = __shfl_up_sync(0xFFFFFFFFu, Xs, d);
        if (lane >= (unsigned)d) {
            Xs = fmaf(Fs, Xo, Xs);   // (Fo,Xo) then (Fs,Xs)
            Fs = Fs * Fo;
        }
    }

    // warp aggregates -> smem (4 warps only)
    __shared__ float sF[TPB / 32];
    __shared__ float sX[TPB / 32];
    if (lane == 31) { sF[warp] = Fs; sX[warp] = Xs; }
    __syncthreads();

    // carry from preceding warps (<= 3 fmas)
    float Xc = 0.0f;
    #pragma unroll
    for (int w = 0; w < TPB / 32; w++) {
        if (w < (int)warp) Xc = fmaf(sF[w], Xc, sX[w]);
    }

    // exclusive-within-warp composite = inclusive of lane-1
    float Fex = __shfl_up_sync(0xFFFFFFFFu, Fs, 1);
    float Xex = __shfl_up_sync(0xFFFFFFFFu, Xs, 1);
    if (lane == 0) { Fex = 1.0f; Xex = 0.0f; }

    float h = fmaf(Fex, Xc, Xex);

    // ---- Phase 3: replay from registers, 4 coalesced streaming stores ----
    float r[EPT];
    #pragma unroll
    for (int j = 0; j < EPT; j++) {
        h = fmaf(fv[j], h, xv[j]);
        r[j] = h;
    }
    float4 o0 = {r[0],  r[1],  r[2],  r[3]};
    float4 o1 = {r[4],  r[5],  r[6],  r[7]};
    float4 o2 = {r[8],  r[9],  r[10], r[11]};
    float4 o3 = {r[12], r[13], r[14], r[15]};
    __stcs(reinterpret_cast<float4*>(out + off),      o0);
    __stcs(reinterpret_cast<float4*>(out + off + 4),  o1);
    __stcs(reinterpret_cast<float4*>(out + off + 8),  o2);
    __stcs(reinterpret_cast<float4*>(out + off + 12), o3);
}

extern "C" void kernel_launch(void* const* d_in, const int* in_sizes, int n_in,
                              void* d_out, int out_size)
{
    const float* f  = (const float*)d_in[0];
    const float* z  = (const float*)d_in[1];
    const float* ig = (const float*)d_in[2];
    float* out = (float*)d_out;

    const int rows = out_size / SEQ;   // 16384
    ifo_scan_kernel<<<rows, TPB>>>(f, z, ig, out);
}

// round 5
// speedup vs baseline: 1.0552x; 1.0470x over previous
#include <cuda_runtime.h>

// IFOPooling: h_t = f_t * h_{t-1} + i_t * z_t over seq (last dim, contiguous).
// [B=16, H=1024, S=2048] fp32 -> 16384 rows of 2048.
//
// R5: block-per-row, TPB=512, EPT=4 -> ~30 regs, 4 CTAs/SM, 64 warps = 100% occ.
// Each thread: 3 front-batched LDG.128, warp shuffle scan, smem scan over
// 16 warp aggregates, replay, 1 STG.128.

#define SEQ 2048
#define TPB 512
#define EPT 4    // elements per thread
#define NW  (TPB / 32)   // 16 warps

__global__ __launch_bounds__(TPB, 4) void ifo_scan_kernel(
    const float* __restrict__ f,
    const float* __restrict__ z,
    const float* __restrict__ ig,
    float* __restrict__ out)
{
    const int row  = blockIdx.x;
    const int base = row * SEQ;
    const int t    = threadIdx.x;
    const int off  = base + t * EPT;

    // ---- Phase 1: 3 coalesced streaming vector loads ----
    float4 fa = __ldcs(reinterpret_cast<const float4*>(f  + off));
    float4 za = __ldcs(reinterpret_cast<const float4*>(z  + off));
    float4 ia = __ldcs(reinterpret_cast<const float4*>(ig + off));

    float fv[EPT] = {fa.x, fa.y, fa.z, fa.w};
    float xv[EPT];
    xv[0] = ia.x * za.x; xv[1] = ia.y * za.y; xv[2] = ia.z * za.z; xv[3] = ia.w * za.w;

    // ---- local segment composite (F, X): h_out = F*h_in + X ----
    float F = 1.0f, X = 0.0f;
    #pragma unroll
    for (int j = 0; j < EPT; j++) {
        X = fmaf(fv[j], X, xv[j]);
        F *= fv[j];
    }

    // ---- Phase 2: inclusive warp scan of composites ----
    const unsigned lane = t & 31u;
    const unsigned warp = t >> 5;
    float Fs = F, Xs = X;
    #pragma unroll
    for (int d = 1; d < 32; d <<= 1) {
        float Fo = __shfl_up_sync(0xFFFFFFFFu, Fs, d);
        float Xo = __shfl_up_sync(0xFFFFFFFFu, Xs, d);
        if (lane >= (unsigned)d) {
            Xs = fmaf(Fs, Xo, Xs);   // (Fo,Xo) then (Fs,Xs)
            Fs = Fs * Fo;
        }
    }

    // warp aggregates -> smem (16 warps)
    __shared__ float sF[NW];
    __shared__ float sX[NW];
    if (lane == 31) { sF[warp] = Fs; sX[warp] = Xs; }
    __syncthreads();

    // carry from preceding warps (<= 15 fmas, registers only)
    float Xc = 0.0f;
    #pragma unroll
    for (int w = 0; w < NW; w++) {
        if (w < (int)warp) Xc = fmaf(sF[w], Xc, sX[w]);
    }

    // exclusive-within-warp composite = inclusive of lane-1
    float Fex = __shfl_up_sync(0xFFFFFFFFu, Fs, 1);
    float Xex = __shfl_up_sync(0xFFFFFFFFu, Xs, 1);
    if (lane == 0) { Fex = 1.0f; Xex = 0.0f; }

    float h = fmaf(Fex, Xc, Xex);

    // ---- Phase 3: replay from registers, 1 coalesced streaming store ----
    float r[EPT];
    #pragma unroll
    for (int j = 0; j < EPT; j++) {
        h = fmaf(fv[j], h, xv[j]);
        r[j] = h;
    }
    float4 oa = {r[0], r[1], r[2], r[3]};
    __stcs(reinterpret_cast<float4*>(out + off), oa);
}

extern "C" void kernel_launch(void* const* d_in, const int* in_sizes, int n_in,
                              void* d_out, int out_size)
{
    const float* f  = (const float*)d_in[0];
    const float* z  = (const float*)d_in[1];
    const float* ig = (const float*)d_in[2];
    float* out = (float*)d_out;

    const int rows = out_size / SEQ;   // 16384
    ifo_scan_kernel<<<rows, TPB>>>(f, z, ig, out);
}

// round 6
// speedup vs baseline: 1.0604x; 1.0049x over previous
#include <cuda_runtime.h>

// IFOPooling: h_t = f_t * h_{t-1} + i_t * z_t over seq (last dim, contiguous).
// [B=16, H=1024, S=2048] fp32 -> 16384 rows of 2048.
//
// R6: R2 shape (block-per-row, TPB=256, EPT=8) with Blackwell 256-bit
// global loads/stores (ld/st.global.v8.f32 -> LDG.E.256/STG.E.256).
// Halves LSU dispatch + L1tex wavefront-queue pressure per byte.

#define SEQ 2048
#define TPB 256
#define EPT 8   // elements per thread

// 256-bit global load: 8 floats, ptr must be 32B-aligned.
__device__ __forceinline__ void ldg256(const float* p, float r[8]) {
    asm volatile(
        "ld.global.L1::evict_first.v8.f32 {%0,%1,%2,%3,%4,%5,%6,%7}, [%8];"
        : "=f"(r[0]), "=f"(r[1]), "=f"(r[2]), "=f"(r[3]),
          "=f"(r[4]), "=f"(r[5]), "=f"(r[6]), "=f"(r[7])
        : "l"(p));
}

// 256-bit global store: 8 floats, ptr must be 32B-aligned.
__device__ __forceinline__ void stg256(float* p, const float r[8]) {
    asm volatile(
        "st.global.L1::evict_first.v8.f32 [%0], {%1,%2,%3,%4,%5,%6,%7,%8};"
        :: "l"(p),
           "f"(r[0]), "f"(r[1]), "f"(r[2]), "f"(r[3]),
           "f"(r[4]), "f"(r[5]), "f"(r[6]), "f"(r[7])
        : "memory");
}

__global__ __launch_bounds__(TPB, 6) void ifo_scan_kernel(
    const float* __restrict__ f,
    const float* __restrict__ z,
    const float* __restrict__ ig,
    float* __restrict__ out)
{
    const int row  = blockIdx.x;
    const int base = row * SEQ;
    const int t    = threadIdx.x;
    const int off  = base + t * EPT;

    // ---- Phase 1: 3 front-batched 256-bit loads ----
    float fv[EPT], zv[EPT], iv[EPT];
    ldg256(f  + off, fv);
    ldg256(z  + off, zv);
    ldg256(ig + off, iv);

    float xv[EPT];
    #pragma unroll
    for (int j = 0; j < EPT; j++) xv[j] = iv[j] * zv[j];

    // local segment composite (F, X): h_out = F*h_in + X
    float F = 1.0f, X = 0.0f;
    #pragma unroll
    for (int j = 0; j < EPT; j++) {
        X = fmaf(fv[j], X, xv[j]);
        F *= fv[j];
    }

    // ---- Phase 2: inclusive warp scan of composites ----
    const unsigned lane = t & 31u;
    const unsigned warp = t >> 5;
    float Fs = F, Xs = X;
    #pragma unroll
    for (int d = 1; d < 32; d <<= 1) {
        float Fo = __shfl_up_sync(0xFFFFFFFFu, Fs, d);
        float Xo = __shfl_up_sync(0xFFFFFFFFu, Xs, d);
        if (lane >= (unsigned)d) {
            Xs = fmaf(Fs, Xo, Xs);   // (Fo,Xo) then (Fs,Xs)
            Fs = Fs * Fo;
        }
    }

    // warp aggregates -> smem (8 warps)
    __shared__ float sF[TPB / 32];
    __shared__ float sX[TPB / 32];
    if (lane == 31) { sF[warp] = Fs; sX[warp] = Xs; }
    __syncthreads();

    // carry from preceding warps (<= 7 fmas)
    float Xc = 0.0f;
    #pragma unroll
    for (int w = 0; w < TPB / 32; w++) {
        if (w < (int)warp) Xc = fmaf(sF[w], Xc, sX[w]);
    }

    // exclusive-within-warp composite = inclusive of lane-1
    float Fex = __shfl_up_sync(0xFFFFFFFFu, Fs, 1);
    float Xex = __shfl_up_sync(0xFFFFFFFFu, Xs, 1);
    if (lane == 0) { Fex = 1.0f; Xex = 0.0f; }

    float h = fmaf(Fex, Xc, Xex);

    // ---- Phase 3: replay from registers, one 256-bit store ----
    float r[EPT];
    #pragma unroll
    for (int j = 0; j < EPT; j++) {
        h = fmaf(fv[j], h, xv[j]);
        r[j] = h;
    }
    stg256(out + off, r);
}

extern "C" void kernel_launch(void* const* d_in, const int* in_sizes, int n_in,
                              void* d_out, int out_size)
{
    const float* f  = (const float*)d_in[0];
    const float* z  = (const float*)d_in[1];
    const float* ig = (const float*)d_in[2];
    float* out = (float*)d_out;

    const int rows = out_size / SEQ;   // 16384
    ifo_scan_kernel<<<rows, TPB>>>(f, z, ig, out);
}